// round 14
// baseline (speedup 1.0000x reference)
#include <cuda_runtime.h>

#define NN 30000
#define EE 480000

// ---- device scratch (no allocs allowed) ----
__device__ float4 g_aggA[NN * 32];   // per node, 32 ch x {s_a, v_a.xyz}
__device__ float4 g_aggB[NN * 32];   // per node, 32 ch x {s_b, v_b.xyz}
__device__ float4 g_xv[NN * 32];     // {x0, y0, y1, y2} per (node, ch)
__device__ int    g_count[NN];
__device__ int    g_offset[NN + 1];
__device__ int    g_cursor[NN];
__device__ int    g_dsts[EE];        // sorted order
__device__ int    g_srcs[EE];        // sorted order
__device__ float  g_pack[EE * 12];   // sorted: {h[8], sh[4]} per edge (48B)

// ---------------------------------------------------------------------------
// Fused node-pre (xv = packed {x0,y0,y1,y2}) + edge histogram.
__global__ void pre_hist_kernel(const float* __restrict__ node_s,
                                const float* __restrict__ node_v,
                                const float* __restrict__ W1_0,
                                const float* __restrict__ W1_1,
                                const int*   __restrict__ edge_src) {
    __shared__ float w0s[1024], w1s[1024];
    for (int i = threadIdx.x; i < 1024; i += blockDim.x) {
        w0s[i] = W1_0[i];
        w1s[i] = W1_1[i];
    }
    __syncthreads();
    int tid = blockIdx.x * blockDim.x + threadIdx.x;
    if (tid < EE) atomicAdd(&g_count[edge_src[tid]], 1);

    int warp = tid >> 5;
    int lane = threadIdx.x & 31;
    if (warp >= NN) return;

    float s  = node_s[warp * 32 + lane];
    float v0 = node_v[warp * 96 + lane * 3 + 0];
    float v1 = node_v[warp * 96 + lane * 3 + 1];
    float v2 = node_v[warp * 96 + lane * 3 + 2];

    float x0 = 0.f, a0 = 0.f, a1 = 0.f, a2 = 0.f;
#pragma unroll
    for (int u = 0; u < 32; u++) {
        float su  = __shfl_sync(0xffffffffu, s,  u);
        float vu0 = __shfl_sync(0xffffffffu, v0, u);
        float vu1 = __shfl_sync(0xffffffffu, v1, u);
        float vu2 = __shfl_sync(0xffffffffu, v2, u);
        float w0 = w0s[u * 32 + lane];
        float w1 = w1s[u * 32 + lane];
        x0 = fmaf(su, w0, x0);
        a0 = fmaf(vu0, w1, a0);
        a1 = fmaf(vu1, w1, a1);
        a2 = fmaf(vu2, w1, a2);
    }
    const float inv_m = 0.17677669529663687f;  // 1/sqrt(32)
    g_xv[warp * 32 + lane] = make_float4(x0 * inv_m, a0 * inv_m,
                                         a1 * inv_m, a2 * inv_m);
}

// ---------------------------------------------------------------------------
__global__ void scan_kernel() {
    __shared__ int ps[1024];
    int tid = threadIdx.x;
    const int CH = 30;
    int base = tid * CH;
    int s = 0;
    for (int i = 0; i < CH; i++) {
        int idx = base + i;
        if (idx < NN) s += g_count[idx];
    }
    ps[tid] = s;
    __syncthreads();
    for (int off = 1; off < 1024; off <<= 1) {
        int t = (tid >= off) ? ps[tid - off] : 0;
        __syncthreads();
        ps[tid] += t;
        __syncthreads();
    }
    int run = ps[tid] - s;
    for (int i = 0; i < CH; i++) {
        int idx = base + i;
        if (idx < NN) {
            g_offset[idx] = run;
            g_cursor[idx] = run;
            run += g_count[idx];
        }
    }
    if (tid == 0) g_offset[NN] = EE;
}

// ---------------------------------------------------------------------------
// Fused scatter + h MLP; writes packed {h[8], sh[4]} record per sorted slot.
__global__ void scatter_h_kernel(const int*   __restrict__ edge_src,
                                 const int*   __restrict__ edge_dst,
                                 const float* __restrict__ edge_scalars,
                                 const float* __restrict__ edge_attr,
                                 const float* __restrict__ Wfc1) {
    __shared__ float fc1s[64];
    if (threadIdx.x < 64) fc1s[threadIdx.x] = Wfc1[threadIdx.x];
    __syncthreads();
    int i = blockIdx.x * blockDim.x + threadIdx.x;
    if (i >= EE) return;

    int s = edge_src[i];
    int p = atomicAdd(&g_cursor[s], 1);
    g_dsts[p] = edge_dst[i];
    g_srcs[p] = s;

    float4 e0 = ((const float4*)(edge_scalars + i * 8))[0];
    float4 e1 = ((const float4*)(edge_scalars + i * 8))[1];
    float es[8] = {e0.x, e0.y, e0.z, e0.w, e1.x, e1.y, e1.z, e1.w};

    const float inv8 = 0.35355339059327373f;  // 1/sqrt(8)
    float h[8];
#pragma unroll
    for (int j = 0; j < 8; j++) {
        float acc = 0.f;
#pragma unroll
        for (int k = 0; k < 8; k++)
            acc = fmaf(es[k], fc1s[k * 8 + j], acc);
        acc *= inv8;
        float ex = __expf(-fabsf(acc));
        h[j] = fmaxf(acc, 0.f) + log1pf(ex) - 0.6931471805599453f;
    }
    float4* rec = (float4*)(g_pack + (size_t)p * 12);
    rec[0] = make_float4(h[0], h[1], h[2], h[3]);
    rec[1] = make_float4(h[4], h[5], h[6], h[7]);
    rec[2] = *(const float4*)(edge_attr + i * 4);
}

// ---------------------------------------------------------------------------
__device__ __forceinline__ void red_v4(float4* addr, float a, float b, float c, float d) {
    asm volatile("red.global.add.v4.f32 [%0], {%1,%2,%3,%4};"
                 :: "l"(addr), "f"(a), "f"(b), "f"(c), "f"(d) : "memory");
}

// ---------------------------------------------------------------------------
// edge_agg8 (measured 43.8us): warp per 16 sorted edges, records staged via
// smem, srcs/dsts in lane registers + shfl, fc2 in registers.
__global__ __launch_bounds__(256, 3)
void edge_agg8_kernel(const float* __restrict__ Wfc2) {
    __shared__ float st_all[8][192];   // per warp: 16 edges x 12 floats
    int wid = threadIdx.x >> 5;
    int lane = threadIdx.x & 31;
    int gw = blockIdx.x * 8 + wid;     // EE/16 = 30000 warps
    float* st = st_all[wid];
    int beg = gw * 16;

    float f00[8], f01[8], f10[8], f11[8];
    const float inv8 = 0.35355339059327373f;
#pragma unroll
    for (int j = 0; j < 8; j++) {
        const float* r = Wfc2 + j * 128 + lane;
        f00[j] = r[0]  * inv8;
        f01[j] = r[32] * inv8;
        f10[j] = r[64] * inv8;
        f11[j] = r[96] * inv8;
    }

    const float4* gp = (const float4*)(g_pack + (size_t)beg * 12);
    ((float4*)st)[lane] = gp[lane];
    if (lane < 16) ((float4*)st)[32 + lane] = gp[32 + lane];
    int srcreg = 0, dstreg = 0;
    if (lane < 16) {
        srcreg = g_srcs[beg + lane];
        dstreg = g_dsts[beg + lane];
    }
    __syncwarp();

    float aA0 = 0.f, aA1 = 0.f, aA2 = 0.f, aA3 = 0.f;
    float aB0 = 0.f, aB1 = 0.f, aB2 = 0.f, aB3 = 0.f;

    int cur = __shfl_sync(0xffffffffu, srcreg, 0);
    float4 xv_c;
    {
        int d0i = __shfl_sync(0xffffffffu, dstreg, 0);
        xv_c = g_xv[d0i * 32 + lane];
    }
    int d_nx = __shfl_sync(0xffffffffu, dstreg, 1);

    const float INV_SQRT3 = 0.5773502691896258f;

#pragma unroll 4
    for (int e = 0; e < 16; e++) {
        float4 xv = xv_c;
        if (e < 15) xv_c = g_xv[d_nx * 32 + lane];
        if (e < 14) d_nx = __shfl_sync(0xffffffffu, dstreg, e + 2);
        int s = __shfl_sync(0xffffffffu, srcreg, e);

        if (s != cur) {   // uniform across warp
            red_v4(&g_aggA[cur * 32 + lane], aA0, aA1, aA2, aA3);
            red_v4(&g_aggB[cur * 32 + lane], aB0, aB1, aB2, aB3);
            aA0 = aA1 = aA2 = aA3 = 0.f;
            aB0 = aB1 = aB2 = aB3 = 0.f;
            cur = s;
        }

        float4 h0 = *(const float4*)&st[e * 12];
        float4 h1 = *(const float4*)&st[e * 12 + 4];
        float4 sh = *(const float4*)&st[e * 12 + 8];

        float w00 = h0.x * f00[0];
        float w01 = h0.x * f01[0];
        float w10 = h0.x * f10[0];
        float w11 = h0.x * f11[0];
        w00 = fmaf(h0.y, f00[1], w00); w01 = fmaf(h0.y, f01[1], w01);
        w10 = fmaf(h0.y, f10[1], w10); w11 = fmaf(h0.y, f11[1], w11);
        w00 = fmaf(h0.z, f00[2], w00); w01 = fmaf(h0.z, f01[2], w01);
        w10 = fmaf(h0.z, f10[2], w10); w11 = fmaf(h0.z, f11[2], w11);
        w00 = fmaf(h0.w, f00[3], w00); w01 = fmaf(h0.w, f01[3], w01);
        w10 = fmaf(h0.w, f10[3], w10); w11 = fmaf(h0.w, f11[3], w11);
        w00 = fmaf(h1.x, f00[4], w00); w01 = fmaf(h1.x, f01[4], w01);
        w10 = fmaf(h1.x, f10[4], w10); w11 = fmaf(h1.x, f11[4], w11);
        w00 = fmaf(h1.y, f00[5], w00); w01 = fmaf(h1.y, f01[5], w01);
        w10 = fmaf(h1.y, f10[5], w10); w11 = fmaf(h1.y, f11[5], w11);
        w00 = fmaf(h1.z, f00[6], w00); w01 = fmaf(h1.z, f01[6], w01);
        w10 = fmaf(h1.z, f10[6], w10); w11 = fmaf(h1.z, f11[6], w11);
        w00 = fmaf(h1.w, f00[7], w00); w01 = fmaf(h1.w, f01[7], w01);
        w10 = fmaf(h1.w, f10[7], w10); w11 = fmaf(h1.w, f11[7], w11);

        float x0 = xv.x, y0 = xv.y, y1 = xv.z, y2 = xv.w;
        float s_a = w00 * x0 * sh.x;
        float dot = fmaf(y0, sh.y, fmaf(y1, sh.z, y2 * sh.w));
        float s_b = w11 * dot * INV_SQRT3;
        float p = w01 * x0;
        float q = w10 * sh.x;

        aA0 += s_a;               aA1 = fmaf(p, sh.y, aA1);
        aA2 = fmaf(p, sh.z, aA2); aA3 = fmaf(p, sh.w, aA3);
        aB0 += s_b;               aB1 = fmaf(q, y0, aB1);
        aB2 = fmaf(q, y1, aB2);   aB3 = fmaf(q, y2, aB3);
    }
    red_v4(&g_aggA[cur * 32 + lane], aA0, aA1, aA2, aA3);
    red_v4(&g_aggB[cur * 32 + lane], aB0, aB1, aB2, aB3);
}

// ---------------------------------------------------------------------------
// node_post7: 3 nodes per warp (30000 = 1250 tiles x 24 nodes exactly).
// Each weight LDS.128 feeds 6 A-chains; chains split into two depth-4 halves.
#define P7_W0LO 0
#define P7_W0HI 4096
#define P7_W1LO 8192
#define P7_W1HI 12288
#define P7_STAGE 16384              /* 8 warps x 384 floats */
#define P7_FLOATS 19456
#define P7_BYTES (P7_FLOATS * 4)
#define P7_TILES 1250

__device__ __forceinline__ float dot8(float4 alo, float4 ahi,
                                      float4 clo, float4 chi) {
    float p = alo.x * clo.x;
    p = fmaf(alo.y, clo.y, p);
    p = fmaf(alo.z, clo.z, p);
    p = fmaf(alo.w, clo.w, p);
    float q = ahi.x * chi.x;
    q = fmaf(ahi.y, chi.y, q);
    q = fmaf(ahi.z, chi.z, q);
    q = fmaf(ahi.w, chi.w, q);
    return p + q;
}

__global__ __launch_bounds__(256, 2)
void node_post7_kernel(const float* __restrict__ node_s,
                       const float* __restrict__ node_v,
                       const float* __restrict__ node_attr,
                       const float* __restrict__ W2_0,
                       const float* __restrict__ W2_1,
                       const float* __restrict__ Wsc0,
                       const float* __restrict__ Wsc1,
                       float* __restrict__ out) {
    extern __shared__ float sm[];
    const float c_agg = 0.03125f;  // 1/sqrt(64)*1/sqrt(16)
    const float c_sc  = 0.0625f;   // 1/sqrt(32*8)
    int tid = threadIdx.x;

    for (int i = tid; i < 8192; i += 256) {
        int u = i >> 8, v = (i >> 5) & 7, w = i & 31;
        int base = (u * 32 + w) * 4 + (v & 3);
        int lo = (v < 4);
        sm[(lo ? P7_W0LO : P7_W0HI) + base] = Wsc0[i] * c_sc;
        sm[(lo ? P7_W1LO : P7_W1HI) + base] = Wsc1[i] * c_sc;
    }
    __syncthreads();

    int wid = tid >> 5, lane = tid & 31;
    float* st = &sm[P7_STAGE + wid * 384];

    for (int tile = blockIdx.x; tile < P7_TILES; tile += gridDim.x) {
        int n0 = tile * 24 + wid * 3;

        // stage 3 nodes: planes {s, v0, v1, v2} x 32
#pragma unroll
        for (int k = 0; k < 3; k++) {
            int n = n0 + k;
            st[k * 128 + lane]       = node_s[n * 32 + lane];
            st[k * 128 + 32 + lane]  = node_v[n * 96 + lane * 3 + 0];
            st[k * 128 + 64 + lane]  = node_v[n * 96 + lane * 3 + 1];
            st[k * 128 + 96 + lane]  = node_v[n * 96 + lane * 3 + 2];
        }
        __syncwarp();

        float4 a0lo = ((const float4*)(node_attr + (n0 + 0) * 8))[0];
        float4 a0hi = ((const float4*)(node_attr + (n0 + 0) * 8))[1];
        float4 a1lo = ((const float4*)(node_attr + (n0 + 1) * 8))[0];
        float4 a1hi = ((const float4*)(node_attr + (n0 + 1) * 8))[1];
        float4 a2lo = ((const float4*)(node_attr + (n0 + 2) * 8))[0];
        float4 a2hi = ((const float4*)(node_attr + (n0 + 2) * 8))[1];

        float S0 = 0.f, S1 = 0.f, S2 = 0.f;
        float V00 = 0.f, V01 = 0.f, V02 = 0.f;
        float V10 = 0.f, V11 = 0.f, V12 = 0.f;
        float V20 = 0.f, V21 = 0.f, V22 = 0.f;

#pragma unroll
        for (int u4 = 0; u4 < 8; u4++) {
            float4 sq0 = *(const float4*)&st[0 * 128 + u4 * 4];
            float4 sq1 = *(const float4*)&st[1 * 128 + u4 * 4];
            float4 sq2 = *(const float4*)&st[2 * 128 + u4 * 4];
            float4 p00 = *(const float4*)&st[0 * 128 + 32 + u4 * 4];
            float4 p01 = *(const float4*)&st[0 * 128 + 64 + u4 * 4];
            float4 p02 = *(const float4*)&st[0 * 128 + 96 + u4 * 4];
            float4 p10 = *(const float4*)&st[1 * 128 + 32 + u4 * 4];
            float4 p11 = *(const float4*)&st[1 * 128 + 64 + u4 * 4];
            float4 p12 = *(const float4*)&st[1 * 128 + 96 + u4 * 4];
            float4 p20 = *(const float4*)&st[2 * 128 + 32 + u4 * 4];
            float4 p21 = *(const float4*)&st[2 * 128 + 64 + u4 * 4];
            float4 p22 = *(const float4*)&st[2 * 128 + 96 + u4 * 4];

#pragma unroll
            for (int j = 0; j < 4; j++) {
                float su0 = j == 0 ? sq0.x : j == 1 ? sq0.y : j == 2 ? sq0.z : sq0.w;
                float su1 = j == 0 ? sq1.x : j == 1 ? sq1.y : j == 2 ? sq1.z : sq1.w;
                float su2 = j == 0 ? sq2.x : j == 1 ? sq2.y : j == 2 ? sq2.z : sq2.w;
                float w00 = j == 0 ? p00.x : j == 1 ? p00.y : j == 2 ? p00.z : p00.w;
                float w01 = j == 0 ? p01.x : j == 1 ? p01.y : j == 2 ? p01.z : p01.w;
                float w02 = j == 0 ? p02.x : j == 1 ? p02.y : j == 2 ? p02.z : p02.w;
                float w10 = j == 0 ? p10.x : j == 1 ? p10.y : j == 2 ? p10.z : p10.w;
                float w11 = j == 0 ? p11.x : j == 1 ? p11.y : j == 2 ? p11.z : p11.w;
                float w12 = j == 0 ? p12.x : j == 1 ? p12.y : j == 2 ? p12.z : p12.w;
                float w20 = j == 0 ? p20.x : j == 1 ? p20.y : j == 2 ? p20.z : p20.w;
                float w21 = j == 0 ? p21.x : j == 1 ? p21.y : j == 2 ? p21.z : p21.w;
                float w22 = j == 0 ? p22.x : j == 1 ? p22.y : j == 2 ? p22.z : p22.w;

                int u = u4 * 4 + j;
                int o = (u * 32 + lane) * 4;
                float4 c0 = *(const float4*)&sm[P7_W0LO + o];
                float4 c1 = *(const float4*)&sm[P7_W0HI + o];
                float4 d0 = *(const float4*)&sm[P7_W1LO + o];
                float4 d1 = *(const float4*)&sm[P7_W1HI + o];

                float A00 = dot8(a0lo, a0hi, c0, c1);
                float A01 = dot8(a1lo, a1hi, c0, c1);
                float A02 = dot8(a2lo, a2hi, c0, c1);
                float A10 = dot8(a0lo, a0hi, d0, d1);
                float A11 = dot8(a1lo, a1hi, d0, d1);
                float A12 = dot8(a2lo, a2hi, d0, d1);

                S0 = fmaf(su0, A00, S0);
                S1 = fmaf(su1, A01, S1);
                S2 = fmaf(su2, A02, S2);
                V00 = fmaf(w00, A10, V00);
                V01 = fmaf(w01, A10, V01);
                V02 = fmaf(w02, A10, V02);
                V10 = fmaf(w10, A11, V10);
                V11 = fmaf(w11, A11, V11);
                V12 = fmaf(w12, A11, V12);
                V20 = fmaf(w20, A12, V20);
                V21 = fmaf(w21, A12, V21);
                V22 = fmaf(w22, A12, V22);
            }
        }

#pragma unroll 4
        for (int k = 0; k < 32; k++) {
            float4 qa0 = g_aggA[(n0 + 0) * 32 + k];
            float4 qa1 = g_aggA[(n0 + 1) * 32 + k];
            float4 qa2 = g_aggA[(n0 + 2) * 32 + k];
            float t0 = W2_0[k * 32 + lane] * c_agg;
            float t1 = W2_1[k * 32 + lane] * c_agg;
            S0 = fmaf(qa0.x, t0, S0);
            V00 = fmaf(qa0.y, t1, V00); V01 = fmaf(qa0.z, t1, V01);
            V02 = fmaf(qa0.w, t1, V02);
            S1 = fmaf(qa1.x, t0, S1);
            V10 = fmaf(qa1.y, t1, V10); V11 = fmaf(qa1.z, t1, V11);
            V12 = fmaf(qa1.w, t1, V12);
            S2 = fmaf(qa2.x, t0, S2);
            V20 = fmaf(qa2.y, t1, V20); V21 = fmaf(qa2.z, t1, V21);
            V22 = fmaf(qa2.w, t1, V22);
        }
#pragma unroll 4
        for (int k = 0; k < 32; k++) {
            float4 qa0 = g_aggB[(n0 + 0) * 32 + k];
            float4 qa1 = g_aggB[(n0 + 1) * 32 + k];
            float4 qa2 = g_aggB[(n0 + 2) * 32 + k];
            float t0 = W2_0[(32 + k) * 32 + lane] * c_agg;
            float t1 = W2_1[(32 + k) * 32 + lane] * c_agg;
            S0 = fmaf(qa0.x, t0, S0);
            V00 = fmaf(qa0.y, t1, V00); V01 = fmaf(qa0.z, t1, V01);
            V02 = fmaf(qa0.w, t1, V02);
            S1 = fmaf(qa1.x, t0, S1);
            V10 = fmaf(qa1.y, t1, V10); V11 = fmaf(qa1.z, t1, V11);
            V12 = fmaf(qa1.w, t1, V12);
            S2 = fmaf(qa2.x, t0, S2);
            V20 = fmaf(qa2.y, t1, V20); V21 = fmaf(qa2.z, t1, V21);
            V22 = fmaf(qa2.w, t1, V22);
        }

        out[(n0 + 0) * 128 + lane] = S0;
        out[(n0 + 0) * 128 + 32 + lane * 3 + 0] = V00;
        out[(n0 + 0) * 128 + 32 + lane * 3 + 1] = V01;
        out[(n0 + 0) * 128 + 32 + lane * 3 + 2] = V02;
        out[(n0 + 1) * 128 + lane] = S1;
        out[(n0 + 1) * 128 + 32 + lane * 3 + 0] = V10;
        out[(n0 + 1) * 128 + 32 + lane * 3 + 1] = V11;
        out[(n0 + 1) * 128 + 32 + lane * 3 + 2] = V12;
        out[(n0 + 2) * 128 + lane] = S2;
        out[(n0 + 2) * 128 + 32 + lane * 3 + 0] = V20;
        out[(n0 + 2) * 128 + 32 + lane * 3 + 1] = V21;
        out[(n0 + 2) * 128 + 32 + lane * 3 + 2] = V22;
        __syncwarp();
    }
}

// ---------------------------------------------------------------------------
extern "C" void kernel_launch(void* const* d_in, const int* in_sizes, int n_in,
                              void* d_out, int out_size) {
    const float* node_s       = (const float*)d_in[0];
    const float* node_v       = (const float*)d_in[1];
    const float* node_attr    = (const float*)d_in[2];
    const float* edge_attr    = (const float*)d_in[3];
    const float* edge_scalars = (const float*)d_in[4];
    const float* W1_0         = (const float*)d_in[5];
    const float* W1_1         = (const float*)d_in[6];
    const float* Wfc1         = (const float*)d_in[7];
    const float* Wfc2         = (const float*)d_in[8];
    const float* W2_0         = (const float*)d_in[9];
    const float* W2_1         = (const float*)d_in[10];
    const float* Wsc0         = (const float*)d_in[11];
    const float* Wsc1         = (const float*)d_in[12];
    const int*   edge_src     = (const int*)d_in[13];
    const int*   edge_dst     = (const int*)d_in[14];
    float* out = (float*)d_out;

    cudaFuncSetAttribute(node_post7_kernel,
                         cudaFuncAttributeMaxDynamicSharedMemorySize, P7_BYTES);

    void* p = 0;
    cudaGetSymbolAddress(&p, g_count);
    cudaMemsetAsync(p, 0, NN * sizeof(int));
    cudaGetSymbolAddress(&p, g_aggA);
    cudaMemsetAsync(p, 0, NN * 32 * sizeof(float4));
    cudaGetSymbolAddress(&p, g_aggB);
    cudaMemsetAsync(p, 0, NN * 32 * sizeof(float4));

    pre_hist_kernel<<<(NN * 32 + 255) / 256, 256>>>(node_s, node_v, W1_0, W1_1,
                                                    edge_src);
    scan_kernel<<<1, 1024>>>();
    scatter_h_kernel<<<(EE + 255) / 256, 256>>>(edge_src, edge_dst,
                                                edge_scalars, edge_attr, Wfc1);
    edge_agg8_kernel<<<EE / 16 / 8, 256>>>(Wfc2);
    node_post7_kernel<<<444, 256, P7_BYTES>>>(node_s, node_v, node_attr,
                                              W2_0, W2_1, Wsc0, Wsc1, out);
}

// round 15
// speedup vs baseline: 1.0787x; 1.0787x over previous
#include <cuda_runtime.h>

#define NN 30000
#define EE 480000

// ---- device scratch (no allocs allowed) ----
__device__ float4 g_aggA[NN * 32];   // per node, 32 ch x {s_a, v_a.xyz}
__device__ float4 g_aggB[NN * 32];   // per node, 32 ch x {s_b, v_b.xyz}
__device__ float4 g_xv[NN * 32];     // {x0, y0, y1, y2} per (node, ch)
__device__ int    g_count[NN];
__device__ int    g_offset[NN + 1];
__device__ int    g_cursor[NN];
__device__ int    g_dsts[EE];        // sorted order
__device__ int    g_srcs[EE];        // sorted order
__device__ float  g_pack[EE * 12];   // sorted: {h[8], sh[4]} per edge (48B)

// ---------------------------------------------------------------------------
// Fused node-pre (xv = packed {x0,y0,y1,y2}) + edge histogram.
__global__ void pre_hist_kernel(const float* __restrict__ node_s,
                                const float* __restrict__ node_v,
                                const float* __restrict__ W1_0,
                                const float* __restrict__ W1_1,
                                const int*   __restrict__ edge_src) {
    __shared__ float w0s[1024], w1s[1024];
    for (int i = threadIdx.x; i < 1024; i += blockDim.x) {
        w0s[i] = W1_0[i];
        w1s[i] = W1_1[i];
    }
    __syncthreads();
    int tid = blockIdx.x * blockDim.x + threadIdx.x;
    if (tid < EE) atomicAdd(&g_count[edge_src[tid]], 1);

    int warp = tid >> 5;
    int lane = threadIdx.x & 31;
    if (warp >= NN) return;

    float s  = node_s[warp * 32 + lane];
    float v0 = node_v[warp * 96 + lane * 3 + 0];
    float v1 = node_v[warp * 96 + lane * 3 + 1];
    float v2 = node_v[warp * 96 + lane * 3 + 2];

    float x0 = 0.f, a0 = 0.f, a1 = 0.f, a2 = 0.f;
#pragma unroll
    for (int u = 0; u < 32; u++) {
        float su  = __shfl_sync(0xffffffffu, s,  u);
        float vu0 = __shfl_sync(0xffffffffu, v0, u);
        float vu1 = __shfl_sync(0xffffffffu, v1, u);
        float vu2 = __shfl_sync(0xffffffffu, v2, u);
        float w0 = w0s[u * 32 + lane];
        float w1 = w1s[u * 32 + lane];
        x0 = fmaf(su, w0, x0);
        a0 = fmaf(vu0, w1, a0);
        a1 = fmaf(vu1, w1, a1);
        a2 = fmaf(vu2, w1, a2);
    }
    const float inv_m = 0.17677669529663687f;  // 1/sqrt(32)
    g_xv[warp * 32 + lane] = make_float4(x0 * inv_m, a0 * inv_m,
                                         a1 * inv_m, a2 * inv_m);
}

// ---------------------------------------------------------------------------
__global__ void scan_kernel() {
    __shared__ int ps[1024];
    int tid = threadIdx.x;
    const int CH = 30;
    int base = tid * CH;
    int s = 0;
    for (int i = 0; i < CH; i++) {
        int idx = base + i;
        if (idx < NN) s += g_count[idx];
    }
    ps[tid] = s;
    __syncthreads();
    for (int off = 1; off < 1024; off <<= 1) {
        int t = (tid >= off) ? ps[tid - off] : 0;
        __syncthreads();
        ps[tid] += t;
        __syncthreads();
    }
    int run = ps[tid] - s;
    for (int i = 0; i < CH; i++) {
        int idx = base + i;
        if (idx < NN) {
            g_offset[idx] = run;
            g_cursor[idx] = run;
            run += g_count[idx];
        }
    }
    if (tid == 0) g_offset[NN] = EE;
}

// ---------------------------------------------------------------------------
// Fused scatter + h MLP; writes packed {h[8], sh[4]} record per sorted slot.
__global__ void scatter_h_kernel(const int*   __restrict__ edge_src,
                                 const int*   __restrict__ edge_dst,
                                 const float* __restrict__ edge_scalars,
                                 const float* __restrict__ edge_attr,
                                 const float* __restrict__ Wfc1) {
    __shared__ float fc1s[64];
    if (threadIdx.x < 64) fc1s[threadIdx.x] = Wfc1[threadIdx.x];
    __syncthreads();
    int i = blockIdx.x * blockDim.x + threadIdx.x;
    if (i >= EE) return;

    int s = edge_src[i];
    int p = atomicAdd(&g_cursor[s], 1);
    g_dsts[p] = edge_dst[i];
    g_srcs[p] = s;

    float4 e0 = ((const float4*)(edge_scalars + i * 8))[0];
    float4 e1 = ((const float4*)(edge_scalars + i * 8))[1];
    float es[8] = {e0.x, e0.y, e0.z, e0.w, e1.x, e1.y, e1.z, e1.w};

    const float inv8 = 0.35355339059327373f;  // 1/sqrt(8)
    float h[8];
#pragma unroll
    for (int j = 0; j < 8; j++) {
        float acc = 0.f;
#pragma unroll
        for (int k = 0; k < 8; k++)
            acc = fmaf(es[k], fc1s[k * 8 + j], acc);
        acc *= inv8;
        float ex = __expf(-fabsf(acc));
        h[j] = fmaxf(acc, 0.f) + log1pf(ex) - 0.6931471805599453f;
    }
    float4* rec = (float4*)(g_pack + (size_t)p * 12);
    rec[0] = make_float4(h[0], h[1], h[2], h[3]);
    rec[1] = make_float4(h[4], h[5], h[6], h[7]);
    rec[2] = *(const float4*)(edge_attr + i * 4);
}

// ---------------------------------------------------------------------------
__device__ __forceinline__ void red_v4(float4* addr, float a, float b, float c, float d) {
    asm volatile("red.global.add.v4.f32 [%0], {%1,%2,%3,%4};"
                 :: "l"(addr), "f"(a), "f"(b), "f"(c), "f"(d) : "memory");
}

// ---------------------------------------------------------------------------
// edge_agg8 (measured 43.8us): warp per 16 sorted edges, records staged via
// smem, srcs/dsts in lane registers + shfl, fc2 in registers.
__global__ __launch_bounds__(256, 3)
void edge_agg8_kernel(const float* __restrict__ Wfc2) {
    __shared__ float st_all[8][192];   // per warp: 16 edges x 12 floats
    int wid = threadIdx.x >> 5;
    int lane = threadIdx.x & 31;
    int gw = blockIdx.x * 8 + wid;     // EE/16 = 30000 warps
    float* st = st_all[wid];
    int beg = gw * 16;

    float f00[8], f01[8], f10[8], f11[8];
    const float inv8 = 0.35355339059327373f;
#pragma unroll
    for (int j = 0; j < 8; j++) {
        const float* r = Wfc2 + j * 128 + lane;
        f00[j] = r[0]  * inv8;
        f01[j] = r[32] * inv8;
        f10[j] = r[64] * inv8;
        f11[j] = r[96] * inv8;
    }

    const float4* gp = (const float4*)(g_pack + (size_t)beg * 12);
    ((float4*)st)[lane] = gp[lane];
    if (lane < 16) ((float4*)st)[32 + lane] = gp[32 + lane];
    int srcreg = 0, dstreg = 0;
    if (lane < 16) {
        srcreg = g_srcs[beg + lane];
        dstreg = g_dsts[beg + lane];
    }
    __syncwarp();

    float aA0 = 0.f, aA1 = 0.f, aA2 = 0.f, aA3 = 0.f;
    float aB0 = 0.f, aB1 = 0.f, aB2 = 0.f, aB3 = 0.f;

    int cur = __shfl_sync(0xffffffffu, srcreg, 0);
    float4 xv_c;
    {
        int d0i = __shfl_sync(0xffffffffu, dstreg, 0);
        xv_c = g_xv[d0i * 32 + lane];
    }
    int d_nx = __shfl_sync(0xffffffffu, dstreg, 1);

    const float INV_SQRT3 = 0.5773502691896258f;

#pragma unroll 4
    for (int e = 0; e < 16; e++) {
        float4 xv = xv_c;
        if (e < 15) xv_c = g_xv[d_nx * 32 + lane];
        if (e < 14) d_nx = __shfl_sync(0xffffffffu, dstreg, e + 2);
        int s = __shfl_sync(0xffffffffu, srcreg, e);

        if (s != cur) {   // uniform across warp
            red_v4(&g_aggA[cur * 32 + lane], aA0, aA1, aA2, aA3);
            red_v4(&g_aggB[cur * 32 + lane], aB0, aB1, aB2, aB3);
            aA0 = aA1 = aA2 = aA3 = 0.f;
            aB0 = aB1 = aB2 = aB3 = 0.f;
            cur = s;
        }

        float4 h0 = *(const float4*)&st[e * 12];
        float4 h1 = *(const float4*)&st[e * 12 + 4];
        float4 sh = *(const float4*)&st[e * 12 + 8];

        float w00 = h0.x * f00[0];
        float w01 = h0.x * f01[0];
        float w10 = h0.x * f10[0];
        float w11 = h0.x * f11[0];
        w00 = fmaf(h0.y, f00[1], w00); w01 = fmaf(h0.y, f01[1], w01);
        w10 = fmaf(h0.y, f10[1], w10); w11 = fmaf(h0.y, f11[1], w11);
        w00 = fmaf(h0.z, f00[2], w00); w01 = fmaf(h0.z, f01[2], w01);
        w10 = fmaf(h0.z, f10[2], w10); w11 = fmaf(h0.z, f11[2], w11);
        w00 = fmaf(h0.w, f00[3], w00); w01 = fmaf(h0.w, f01[3], w01);
        w10 = fmaf(h0.w, f10[3], w10); w11 = fmaf(h0.w, f11[3], w11);
        w00 = fmaf(h1.x, f00[4], w00); w01 = fmaf(h1.x, f01[4], w01);
        w10 = fmaf(h1.x, f10[4], w10); w11 = fmaf(h1.x, f11[4], w11);
        w00 = fmaf(h1.y, f00[5], w00); w01 = fmaf(h1.y, f01[5], w01);
        w10 = fmaf(h1.y, f10[5], w10); w11 = fmaf(h1.y, f11[5], w11);
        w00 = fmaf(h1.z, f00[6], w00); w01 = fmaf(h1.z, f01[6], w01);
        w10 = fmaf(h1.z, f10[6], w10); w11 = fmaf(h1.z, f11[6], w11);
        w00 = fmaf(h1.w, f00[7], w00); w01 = fmaf(h1.w, f01[7], w01);
        w10 = fmaf(h1.w, f10[7], w10); w11 = fmaf(h1.w, f11[7], w11);

        float x0 = xv.x, y0 = xv.y, y1 = xv.z, y2 = xv.w;
        float s_a = w00 * x0 * sh.x;
        float dot = fmaf(y0, sh.y, fmaf(y1, sh.z, y2 * sh.w));
        float s_b = w11 * dot * INV_SQRT3;
        float p = w01 * x0;
        float q = w10 * sh.x;

        aA0 += s_a;               aA1 = fmaf(p, sh.y, aA1);
        aA2 = fmaf(p, sh.z, aA2); aA3 = fmaf(p, sh.w, aA3);
        aB0 += s_b;               aB1 = fmaf(q, y0, aB1);
        aB2 = fmaf(q, y1, aB2);   aB3 = fmaf(q, y2, aB3);
    }
    red_v4(&g_aggA[cur * 32 + lane], aA0, aA1, aA2, aA3);
    red_v4(&g_aggB[cur * 32 + lane], aB0, aB1, aB2, aB3);
}

// ---------------------------------------------------------------------------
// node_post8: post7 + the agg8 lesson applied to the W2 phase:
//  - W2_0/W2_1 pre-scaled in smem (conflict-free per-lane LDS)
//  - per warp-tile, 3 nodes' aggA/aggB staged with 6 coalesced LDG.128 +
//    6 STS into the per-warp slab (reused after the A-phase), then the
//    combined k-loop reads them as broadcast LDS.128. LDG/tile: 320 -> 6.
#define P8_W0LO 0
#define P8_W0HI 4096
#define P8_W1LO 8192
#define P8_W1HI 12288
#define P8_W2   16384               /* 4096 floats: W2_0|W2_1, pre-scaled */
#define P8_STAGE 20480              /* 8 warps x 768 floats */
#define P8_FLOATS 26624
#define P8_BYTES (P8_FLOATS * 4)    /* 106,496 B -> 2 blocks/SM */
#define P8_TILES 1250

__device__ __forceinline__ float dot8(float4 alo, float4 ahi,
                                      float4 clo, float4 chi) {
    float p = alo.x * clo.x;
    p = fmaf(alo.y, clo.y, p);
    p = fmaf(alo.z, clo.z, p);
    p = fmaf(alo.w, clo.w, p);
    float q = ahi.x * chi.x;
    q = fmaf(ahi.y, chi.y, q);
    q = fmaf(ahi.z, chi.z, q);
    q = fmaf(ahi.w, chi.w, q);
    return p + q;
}

__global__ __launch_bounds__(256, 2)
void node_post8_kernel(const float* __restrict__ node_s,
                       const float* __restrict__ node_v,
                       const float* __restrict__ node_attr,
                       const float* __restrict__ W2_0,
                       const float* __restrict__ W2_1,
                       const float* __restrict__ Wsc0,
                       const float* __restrict__ Wsc1,
                       float* __restrict__ out) {
    extern __shared__ float sm[];
    const float c_agg = 0.03125f;  // 1/sqrt(64)*1/sqrt(16)
    const float c_sc  = 0.0625f;   // 1/sqrt(32*8)
    int tid = threadIdx.x;

    for (int i = tid; i < 8192; i += 256) {
        int u = i >> 8, v = (i >> 5) & 7, w = i & 31;
        int base = (u * 32 + w) * 4 + (v & 3);
        int lo = (v < 4);
        sm[(lo ? P8_W0LO : P8_W0HI) + base] = Wsc0[i] * c_sc;
        sm[(lo ? P8_W1LO : P8_W1HI) + base] = Wsc1[i] * c_sc;
    }
    for (int i = tid; i < 2048; i += 256) {
        sm[P8_W2 + i]        = W2_0[i] * c_agg;
        sm[P8_W2 + 2048 + i] = W2_1[i] * c_agg;
    }
    __syncthreads();

    int wid = tid >> 5, lane = tid & 31;
    float* st = &sm[P8_STAGE + wid * 768];

    for (int tile = blockIdx.x; tile < P8_TILES; tile += gridDim.x) {
        int n0 = tile * 24 + wid * 3;

        // ---- phase 1: stage 3 nodes' s/v planes (384 floats of slab) ----
#pragma unroll
        for (int k = 0; k < 3; k++) {
            int n = n0 + k;
            st[k * 128 + lane]       = node_s[n * 32 + lane];
            st[k * 128 + 32 + lane]  = node_v[n * 96 + lane * 3 + 0];
            st[k * 128 + 64 + lane]  = node_v[n * 96 + lane * 3 + 1];
            st[k * 128 + 96 + lane]  = node_v[n * 96 + lane * 3 + 2];
        }
        __syncwarp();

        float4 a0lo = ((const float4*)(node_attr + (n0 + 0) * 8))[0];
        float4 a0hi = ((const float4*)(node_attr + (n0 + 0) * 8))[1];
        float4 a1lo = ((const float4*)(node_attr + (n0 + 1) * 8))[0];
        float4 a1hi = ((const float4*)(node_attr + (n0 + 1) * 8))[1];
        float4 a2lo = ((const float4*)(node_attr + (n0 + 2) * 8))[0];
        float4 a2hi = ((const float4*)(node_attr + (n0 + 2) * 8))[1];

        float S0 = 0.f, S1 = 0.f, S2 = 0.f;
        float V00 = 0.f, V01 = 0.f, V02 = 0.f;
        float V10 = 0.f, V11 = 0.f, V12 = 0.f;
        float V20 = 0.f, V21 = 0.f, V22 = 0.f;

#pragma unroll
        for (int u4 = 0; u4 < 8; u4++) {
            float4 sq0 = *(const float4*)&st[0 * 128 + u4 * 4];
            float4 sq1 = *(const float4*)&st[1 * 128 + u4 * 4];
            float4 sq2 = *(const float4*)&st[2 * 128 + u4 * 4];
            float4 p00 = *(const float4*)&st[0 * 128 + 32 + u4 * 4];
            float4 p01 = *(const float4*)&st[0 * 128 + 64 + u4 * 4];
            float4 p02 = *(const float4*)&st[0 * 128 + 96 + u4 * 4];
            float4 p10 = *(const float4*)&st[1 * 128 + 32 + u4 * 4];
            float4 p11 = *(const float4*)&st[1 * 128 + 64 + u4 * 4];
            float4 p12 = *(const float4*)&st[1 * 128 + 96 + u4 * 4];
            float4 p20 = *(const float4*)&st[2 * 128 + 32 + u4 * 4];
            float4 p21 = *(const float4*)&st[2 * 128 + 64 + u4 * 4];
            float4 p22 = *(const float4*)&st[2 * 128 + 96 + u4 * 4];

#pragma unroll
            for (int j = 0; j < 4; j++) {
                float su0 = j == 0 ? sq0.x : j == 1 ? sq0.y : j == 2 ? sq0.z : sq0.w;
                float su1 = j == 0 ? sq1.x : j == 1 ? sq1.y : j == 2 ? sq1.z : sq1.w;
                float su2 = j == 0 ? sq2.x : j == 1 ? sq2.y : j == 2 ? sq2.z : sq2.w;
                float w00 = j == 0 ? p00.x : j == 1 ? p00.y : j == 2 ? p00.z : p00.w;
                float w01 = j == 0 ? p01.x : j == 1 ? p01.y : j == 2 ? p01.z : p01.w;
                float w02 = j == 0 ? p02.x : j == 1 ? p02.y : j == 2 ? p02.z : p02.w;
                float w10 = j == 0 ? p10.x : j == 1 ? p10.y : j == 2 ? p10.z : p10.w;
                float w11 = j == 0 ? p11.x : j == 1 ? p11.y : j == 2 ? p11.z : p11.w;
                float w12 = j == 0 ? p12.x : j == 1 ? p12.y : j == 2 ? p12.z : p12.w;
                float w20 = j == 0 ? p20.x : j == 1 ? p20.y : j == 2 ? p20.z : p20.w;
                float w21 = j == 0 ? p21.x : j == 1 ? p21.y : j == 2 ? p21.z : p21.w;
                float w22 = j == 0 ? p22.x : j == 1 ? p22.y : j == 2 ? p22.z : p22.w;

                int u = u4 * 4 + j;
                int o = (u * 32 + lane) * 4;
                float4 c0 = *(const float4*)&sm[P8_W0LO + o];
                float4 c1 = *(const float4*)&sm[P8_W0HI + o];
                float4 d0 = *(const float4*)&sm[P8_W1LO + o];
                float4 d1 = *(const float4*)&sm[P8_W1HI + o];

                float A00 = dot8(a0lo, a0hi, c0, c1);
                float A01 = dot8(a1lo, a1hi, c0, c1);
                float A02 = dot8(a2lo, a2hi, c0, c1);
                float A10 = dot8(a0lo, a0hi, d0, d1);
                float A11 = dot8(a1lo, a1hi, d0, d1);
                float A12 = dot8(a2lo, a2hi, d0, d1);

                S0 = fmaf(su0, A00, S0);
                S1 = fmaf(su1, A01, S1);
                S2 = fmaf(su2, A02, S2);
                V00 = fmaf(w00, A10, V00);
                V01 = fmaf(w01, A10, V01);
                V02 = fmaf(w02, A10, V02);
                V10 = fmaf(w10, A11, V10);
                V11 = fmaf(w11, A11, V11);
                V12 = fmaf(w12, A11, V12);
                V20 = fmaf(w20, A12, V20);
                V21 = fmaf(w21, A12, V21);
                V22 = fmaf(w22, A12, V22);
            }
        }
        __syncwarp();

        // ---- phase 2: stage 3 nodes' aggA/aggB (768 floats, reuse slab) ----
        {
            float4 qa0 = g_aggA[(n0 + 0) * 32 + lane];
            float4 qa1 = g_aggA[(n0 + 1) * 32 + lane];
            float4 qa2 = g_aggA[(n0 + 2) * 32 + lane];
            float4 qb0 = g_aggB[(n0 + 0) * 32 + lane];
            float4 qb1 = g_aggB[(n0 + 1) * 32 + lane];
            float4 qb2 = g_aggB[(n0 + 2) * 32 + lane];
            *(float4*)&st[lane * 4]       = qa0;
            *(float4*)&st[128 + lane * 4] = qa1;
            *(float4*)&st[256 + lane * 4] = qa2;
            *(float4*)&st[384 + lane * 4] = qb0;
            *(float4*)&st[512 + lane * 4] = qb1;
            *(float4*)&st[640 + lane * 4] = qb2;
        }
        __syncwarp();

        // ---- W2 phase: broadcast LDS for agg, coalesced LDS for W2 ----
#pragma unroll 4
        for (int k = 0; k < 32; k++) {
            float4 qa0 = *(const float4*)&st[k * 4];
            float4 qa1 = *(const float4*)&st[128 + k * 4];
            float4 qa2 = *(const float4*)&st[256 + k * 4];
            float4 qb0 = *(const float4*)&st[384 + k * 4];
            float4 qb1 = *(const float4*)&st[512 + k * 4];
            float4 qb2 = *(const float4*)&st[640 + k * 4];
            float t0a = sm[P8_W2 + k * 32 + lane];
            float t1a = sm[P8_W2 + 2048 + k * 32 + lane];
            float t0b = sm[P8_W2 + (32 + k) * 32 + lane];
            float t1b = sm[P8_W2 + 2048 + (32 + k) * 32 + lane];

            S0 = fmaf(qa0.x, t0a, S0);
            V00 = fmaf(qa0.y, t1a, V00); V01 = fmaf(qa0.z, t1a, V01);
            V02 = fmaf(qa0.w, t1a, V02);
            S1 = fmaf(qa1.x, t0a, S1);
            V10 = fmaf(qa1.y, t1a, V10); V11 = fmaf(qa1.z, t1a, V11);
            V12 = fmaf(qa1.w, t1a, V12);
            S2 = fmaf(qa2.x, t0a, S2);
            V20 = fmaf(qa2.y, t1a, V20); V21 = fmaf(qa2.z, t1a, V21);
            V22 = fmaf(qa2.w, t1a, V22);

            S0 = fmaf(qb0.x, t0b, S0);
            V00 = fmaf(qb0.y, t1b, V00); V01 = fmaf(qb0.z, t1b, V01);
            V02 = fmaf(qb0.w, t1b, V02);
            S1 = fmaf(qb1.x, t0b, S1);
            V10 = fmaf(qb1.y, t1b, V10); V11 = fmaf(qb1.z, t1b, V11);
            V12 = fmaf(qb1.w, t1b, V12);
            S2 = fmaf(qb2.x, t0b, S2);
            V20 = fmaf(qb2.y, t1b, V20); V21 = fmaf(qb2.z, t1b, V21);
            V22 = fmaf(qb2.w, t1b, V22);
        }

        out[(n0 + 0) * 128 + lane] = S0;
        out[(n0 + 0) * 128 + 32 + lane * 3 + 0] = V00;
        out[(n0 + 0) * 128 + 32 + lane * 3 + 1] = V01;
        out[(n0 + 0) * 128 + 32 + lane * 3 + 2] = V02;
        out[(n0 + 1) * 128 + lane] = S1;
        out[(n0 + 1) * 128 + 32 + lane * 3 + 0] = V10;
        out[(n0 + 1) * 128 + 32 + lane * 3 + 1] = V11;
        out[(n0 + 1) * 128 + 32 + lane * 3 + 2] = V12;
        out[(n0 + 2) * 128 + lane] = S2;
        out[(n0 + 2) * 128 + 32 + lane * 3 + 0] = V20;
        out[(n0 + 2) * 128 + 32 + lane * 3 + 1] = V21;
        out[(n0 + 2) * 128 + 32 + lane * 3 + 2] = V22;
        __syncwarp();
    }
}

// ---------------------------------------------------------------------------
extern "C" void kernel_launch(void* const* d_in, const int* in_sizes, int n_in,
                              void* d_out, int out_size) {
    const float* node_s       = (const float*)d_in[0];
    const float* node_v       = (const float*)d_in[1];
    const float* node_attr    = (const float*)d_in[2];
    const float* edge_attr    = (const float*)d_in[3];
    const float* edge_scalars = (const float*)d_in[4];
    const float* W1_0         = (const float*)d_in[5];
    const float* W1_1         = (const float*)d_in[6];
    const float* Wfc1         = (const float*)d_in[7];
    const float* Wfc2         = (const float*)d_in[8];
    const float* W2_0         = (const float*)d_in[9];
    const float* W2_1         = (const float*)d_in[10];
    const float* Wsc0         = (const float*)d_in[11];
    const float* Wsc1         = (const float*)d_in[12];
    const int*   edge_src     = (const int*)d_in[13];
    const int*   edge_dst     = (const int*)d_in[14];
    float* out = (float*)d_out;

    cudaFuncSetAttribute(node_post8_kernel,
                         cudaFuncAttributeMaxDynamicSharedMemorySize, P8_BYTES);

    void* p = 0;
    cudaGetSymbolAddress(&p, g_count);
    cudaMemsetAsync(p, 0, NN * sizeof(int));
    cudaGetSymbolAddress(&p, g_aggA);
    cudaMemsetAsync(p, 0, NN * 32 * sizeof(float4));
    cudaGetSymbolAddress(&p, g_aggB);
    cudaMemsetAsync(p, 0, NN * 32 * sizeof(float4));

    pre_hist_kernel<<<(NN * 32 + 255) / 256, 256>>>(node_s, node_v, W1_0, W1_1,
                                                    edge_src);
    scan_kernel<<<1, 1024>>>();
    scatter_h_kernel<<<(EE + 255) / 256, 256>>>(edge_src, edge_dst,
                                                edge_scalars, edge_attr, Wfc1);
    edge_agg8_kernel<<<EE / 16 / 8, 256>>>(Wfc2);
    node_post8_kernel<<<444, 256, P8_BYTES>>>(node_s, node_v, node_attr,
                                              W2_0, W2_1, Wsc0, Wsc1, out);
}